// round 1
// baseline (speedup 1.0000x reference)
#include <cuda_runtime.h>
#include <math.h>

#define CC   256
#define K3   768
#define HWL  3136
#define NBAT 16
#define WD   56
#define HALF_PI 1.5707963f
#define INV56   (1.0f / 56.0f)
#define RS768   0.03608439182435161f   // 1/sqrt(768)

// Scratch (device globals — no allocations allowed)
__device__ float g_t3[NBAT * CC * HWL];   // (n, c, hw)   51.4 MB
__device__ float g_t7[NBAT * K3 * CC];    // (n, 3c, c)   12.6 MB

// Common tile config: BM=128 (rows), BN=64 (cols), BK=8, 256 threads, each 8x4.

// ---------------------------------------------------------------------------
// Stage 1: t3[n,o,p] = sum_k W3[o,k] * t1[n,k,p]
//   t1[n, k=3c+tap, p] = x[n, c, h, w + 2*tap - 2] (zero pad in w)
// ---------------------------------------------------------------------------
__global__ __launch_bounds__(256) void k_t3(const float* __restrict__ x,
                                            const float* __restrict__ W3) {
    __shared__ __align__(16) float As[8][132];
    __shared__ __align__(16) float Bs[8][68];
    const int n  = blockIdx.z;
    const int m0 = blockIdx.y * 128;   // o tile
    const int p0 = blockIdx.x * 64;    // p tile (3136 = 49*64 exact)
    const int t  = threadIdx.x;
    const int tx = t & 15, ty = t >> 4;
    const float* xb = x + (size_t)n * (CC * HWL);

    float acc[8][4];
#pragma unroll
    for (int i = 0; i < 8; i++)
#pragma unroll
        for (int j = 0; j < 4; j++) acc[i][j] = 0.f;

    for (int k0 = 0; k0 < K3; k0 += 8) {
        // A: W3 tile, contiguous-k reads
#pragma unroll
        for (int q = 0; q < 4; q++) {
            int idx = t + 256 * q;
            int kk = idx & 7, m = idx >> 3;
            As[kk][m] = W3[(m0 + m) * K3 + k0 + kk];
        }
        // B: t1 tile generated on the fly
#pragma unroll
        for (int q = 0; q < 2; q++) {
            int idx = t + 256 * q;
            int kk = idx >> 6, pn = idx & 63;
            int k = k0 + kk;
            int c = k / 3, tap = k - 3 * c;
            int p = p0 + pn;
            int w = p % WD;
            int ws = w + 2 * tap - 2;
            float v = 0.f;
            if (ws >= 0 && ws < WD) v = xb[c * HWL + p + (ws - w)];
            Bs[kk][pn] = v;
        }
        __syncthreads();
#pragma unroll
        for (int kk = 0; kk < 8; kk++) {
            const float4* ap = reinterpret_cast<const float4*>(&As[kk][ty * 8]);
            float4 a0 = ap[0], a1 = ap[1];
            float4 b  = *reinterpret_cast<const float4*>(&Bs[kk][tx * 4]);
            float a[8] = {a0.x, a0.y, a0.z, a0.w, a1.x, a1.y, a1.z, a1.w};
            float bb[4] = {b.x, b.y, b.z, b.w};
#pragma unroll
            for (int i = 0; i < 8; i++)
#pragma unroll
                for (int j = 0; j < 4; j++) acc[i][j] = fmaf(a[i], bb[j], acc[i][j]);
        }
        __syncthreads();
    }
    float* t3b = g_t3 + (size_t)n * (CC * HWL);
#pragma unroll
    for (int i = 0; i < 8; i++) {
        int m = m0 + ty * 8 + i;
#pragma unroll
        for (int j = 0; j < 4; j++)
            t3b[m * HWL + p0 + tx * 4 + j] = acc[i][j];
    }
}

// ---------------------------------------------------------------------------
// Stage 2: t7[n,k,c'] = p7w[k,c'] * (1/56) * sum_p t2[n,k,p] * x[n,c',p]
//   t2[n, k=3c+tap, p] = x[n, (c-1)%C, h, w + 2*tap - 2]  (channel roll +1)
// ---------------------------------------------------------------------------
__global__ __launch_bounds__(256) void k_t7(const float* __restrict__ x,
                                            const float* __restrict__ p7w) {
    __shared__ __align__(16) float As[8][132];
    __shared__ __align__(16) float Bs[8][68];
    const int n  = blockIdx.z;
    const int m0 = blockIdx.y * 128;   // k-row tile (768 = 6*128)
    const int c0 = blockIdx.x * 64;    // c' tile   (256 = 4*64)
    const int t  = threadIdx.x;
    const int tx = t & 15, ty = t >> 4;
    const float* xb = x + (size_t)n * (CC * HWL);

    float acc[8][4];
#pragma unroll
    for (int i = 0; i < 8; i++)
#pragma unroll
        for (int j = 0; j < 4; j++) acc[i][j] = 0.f;

    for (int p0 = 0; p0 < HWL; p0 += 8) {      // 3136 = 392*8 exact
        // A: t2 tile, transposed into smem, contiguous-p reads
#pragma unroll
        for (int q = 0; q < 4; q++) {
            int idx = t + 256 * q;
            int pp = idx & 7, m = idx >> 3;
            int k = m0 + m;
            int c = k / 3, tap = k - 3 * c;
            int csrc = (c + CC - 1) & (CC - 1);
            int p = p0 + pp;
            int w = p % WD;
            int ws = w + 2 * tap - 2;
            float v = 0.f;
            if (ws >= 0 && ws < WD) v = xb[csrc * HWL + p + (ws - w)];
            As[pp][m] = v;
        }
        // B: x tile, transposed into smem
#pragma unroll
        for (int q = 0; q < 2; q++) {
            int idx = t + 256 * q;
            int pp = idx & 7, cn = idx >> 3;
            Bs[pp][cn] = xb[(c0 + cn) * HWL + p0 + pp];
        }
        __syncthreads();
#pragma unroll
        for (int pp = 0; pp < 8; pp++) {
            const float4* ap = reinterpret_cast<const float4*>(&As[pp][ty * 8]);
            float4 a0 = ap[0], a1 = ap[1];
            float4 b  = *reinterpret_cast<const float4*>(&Bs[pp][tx * 4]);
            float a[8] = {a0.x, a0.y, a0.z, a0.w, a1.x, a1.y, a1.z, a1.w};
            float bb[4] = {b.x, b.y, b.z, b.w};
#pragma unroll
            for (int i = 0; i < 8; i++)
#pragma unroll
                for (int j = 0; j < 4; j++) acc[i][j] = fmaf(a[i], bb[j], acc[i][j]);
        }
        __syncthreads();
    }
    float* t7b = g_t7 + (size_t)n * (K3 * CC);
#pragma unroll
    for (int i = 0; i < 8; i++) {
        int k = m0 + ty * 8 + i;
#pragma unroll
        for (int j = 0; j < 4; j++) {
            int cp = c0 + tx * 4 + j;
            t7b[k * CC + cp] = acc[i][j] * INV56 * p7w[k * CC + cp];
        }
    }
}

// ---------------------------------------------------------------------------
// Stage 3: out[n,c',p] = (1/sqrt(768)) * sum_k t7[n,k,c'] * t6[n,k,p]
//   t6[n, k=3c+tap, p] = max(t3[n,c,p], sin(HALF_PI * t1[n,k,p]))
// ---------------------------------------------------------------------------
__global__ __launch_bounds__(256) void k_out(const float* __restrict__ x,
                                             float* __restrict__ out) {
    __shared__ __align__(16) float As[8][132];
    __shared__ __align__(16) float Bs[8][68];
    const int n  = blockIdx.z;
    const int m0 = blockIdx.y * 128;   // c' tile (256 = 2*128)
    const int p0 = blockIdx.x * 64;    // p tile  (3136 = 49*64)
    const int t  = threadIdx.x;
    const int tx = t & 15, ty = t >> 4;
    const float* xb  = x   + (size_t)n * (CC * HWL);
    const float* t3b = g_t3 + (size_t)n * (CC * HWL);
    const float* t7b = g_t7 + (size_t)n * (K3 * CC);

    float acc[8][4];
#pragma unroll
    for (int i = 0; i < 8; i++)
#pragma unroll
        for (int j = 0; j < 4; j++) acc[i][j] = 0.f;

    for (int k0 = 0; k0 < K3; k0 += 8) {
        // A: t7 tile, contiguous-c' reads
#pragma unroll
        for (int q = 0; q < 4; q++) {
            int idx = t + 256 * q;
            int kk = idx >> 7, m = idx & 127;
            As[kk][m] = t7b[(k0 + kk) * CC + m0 + m];
        }
        // B: t6 tile generated on the fly
#pragma unroll
        for (int q = 0; q < 2; q++) {
            int idx = t + 256 * q;
            int kk = idx >> 6, pn = idx & 63;
            int k = k0 + kk;
            int c = k / 3, tap = k - 3 * c;
            int p = p0 + pn;
            int w = p % WD;
            int ws = w + 2 * tap - 2;
            float s = 0.f;   // sin(0) for padded region
            if (ws >= 0 && ws < WD) s = sinf(HALF_PI * xb[c * HWL + p + (ws - w)]);
            Bs[kk][pn] = fmaxf(t3b[c * HWL + p], s);
        }
        __syncthreads();
#pragma unroll
        for (int kk = 0; kk < 8; kk++) {
            const float4* ap = reinterpret_cast<const float4*>(&As[kk][ty * 8]);
            float4 a0 = ap[0], a1 = ap[1];
            float4 b  = *reinterpret_cast<const float4*>(&Bs[kk][tx * 4]);
            float a[8] = {a0.x, a0.y, a0.z, a0.w, a1.x, a1.y, a1.z, a1.w};
            float bb[4] = {b.x, b.y, b.z, b.w};
#pragma unroll
            for (int i = 0; i < 8; i++)
#pragma unroll
                for (int j = 0; j < 4; j++) acc[i][j] = fmaf(a[i], bb[j], acc[i][j]);
        }
        __syncthreads();
    }
#pragma unroll
    for (int i = 0; i < 8; i++) {
        int cp = m0 + ty * 8 + i;
#pragma unroll
        for (int j = 0; j < 4; j++)
            out[((size_t)n * CC + cp) * HWL + p0 + tx * 4 + j] = acc[i][j] * RS768;
    }
}

extern "C" void kernel_launch(void* const* d_in, const int* in_sizes, int n_in,
                              void* d_out, int out_size) {
    const float* x   = (const float*)d_in[0];   // (16, 256, 56, 56)
    const float* W3  = (const float*)d_in[1];   // (256, 768)
    const float* p7w = (const float*)d_in[2];   // (1, 256, 3, 256)
    float* out = (float*)d_out;                 // (16, 256, 56, 56)

    dim3 blk(256);
    k_t3 <<<dim3(49, 2, 16), blk>>>(x, W3);
    k_t7 <<<dim3(4, 6, 16), blk>>>(x, p7w);
    k_out<<<dim3(49, 2, 16), blk>>>(x, out);
}

// round 3
// speedup vs baseline: 2.2670x; 2.2670x over previous
#include <cuda_runtime.h>
#include <cstdint>
#include <math.h>

#define CC   256
#define K3   768
#define HWL  3136
#define WD   56
#define HALF_PI 1.5707963f
#define INV56   (1.0f / 56.0f)
#define RS768   0.03608439182435161f   // 1/sqrt(768)

// Scratch (device globals — no allocations allowed)
__device__ float g_t3[16 * CC * HWL];   // (n, c, hw)
__device__ float g_t7[16 * K3 * CC];    // (n, 3c, c)

static __device__ __forceinline__ uint32_t f2tf(float f) {
    uint32_t u; asm("cvt.rna.tf32.f32 %0, %1;" : "=r"(u) : "f"(f)); return u;
}

static __device__ __forceinline__ void mma8(float d[4], const uint32_t a[4], const uint32_t b[2]) {
    asm volatile(
        "mma.sync.aligned.m16n8k8.row.col.f32.tf32.tf32.f32 "
        "{%0,%1,%2,%3},{%4,%5,%6,%7},{%8,%9},{%0,%1,%2,%3};"
        : "+f"(d[0]), "+f"(d[1]), "+f"(d[2]), "+f"(d[3])
        : "r"(a[0]), "r"(a[1]), "r"(a[2]), "r"(a[3]), "r"(b[0]), "r"(b[1]));
}

// =====================================================================
// Stage 1: t3[n,o,p] = sum_k W3[o,k] * t1[n,k,p]
//   A = W3 (row-major [m][k]) in smem [128][20]
//   B = t1 (k-major  [k][p])  in smem [16][136]
// =====================================================================
__global__ __launch_bounds__(256) void k1(const float* __restrict__ x,
                                          const float* __restrict__ W3) {
    __shared__ uint32_t As[128 * 20];
    __shared__ uint32_t Bs[16 * 136];
    const int t = threadIdx.x, lane = t & 31, warp = t >> 5;
    const int n = blockIdx.z, m0 = blockIdx.y * 128, p0 = blockIdx.x * 128;
    const int wm = (warp & 1) * 64, wn = (warp >> 1) * 32;
    const float* xb = x + (size_t)n * (CC * HWL);

    float acc[4][4][4];
#pragma unroll
    for (int i = 0; i < 4; i++)
#pragma unroll
        for (int j = 0; j < 4; j++)
#pragma unroll
            for (int r = 0; r < 4; r++) acc[i][j][r] = 0.f;

    const int am = t >> 1, ak = (t & 1) * 8;        // A gen: row m, 8 k
    const int bk = t >> 4, bp = (t & 15) * 8;       // B gen: row k, 8 p
    const int pB = p0 + bp;
    const bool pOK = pB < HWL;
    const int w0 = pOK ? pB % WD : 0;
    const float* wrow = W3 + (size_t)(m0 + am) * K3;

    float va[8], vb[8];
    auto loadT = [&](int kb) {
        int k0 = kb * 16;
        float4 a0 = *reinterpret_cast<const float4*>(wrow + k0 + ak);
        float4 a1 = *reinterpret_cast<const float4*>(wrow + k0 + ak + 4);
        va[0]=a0.x; va[1]=a0.y; va[2]=a0.z; va[3]=a0.w;
        va[4]=a1.x; va[5]=a1.y; va[6]=a1.z; va[7]=a1.w;
        int k = k0 + bk;
        int c = k / 3, tap = k - 3 * c;
        int sh = 2 * tap - 2;
        const float* src = xb + (size_t)c * HWL + pB + sh;
#pragma unroll
        for (int j = 0; j < 8; j++) {
            vb[j] = (pOK && (unsigned)(w0 + j + sh) < WD) ? src[j] : 0.f;
        }
    };
    auto storeT = [&]() {
#pragma unroll
        for (int j = 0; j < 8; j++) As[am * 20 + ak + j] = f2tf(va[j]);
#pragma unroll
        for (int j = 0; j < 8; j++) Bs[bk * 136 + bp + j] = f2tf(vb[j]);
    };
    auto compute = [&]() {
#pragma unroll
        for (int kk = 0; kk < 16; kk += 8) {
            uint32_t af[4][4], bf[4][2];
            int cL = kk + (lane & 3);
#pragma unroll
            for (int mt = 0; mt < 4; mt++) {
                int r = wm + mt * 16 + (lane >> 2);
                af[mt][0] = As[r * 20 + cL];
                af[mt][1] = As[(r + 8) * 20 + cL];
                af[mt][2] = As[r * 20 + cL + 4];
                af[mt][3] = As[(r + 8) * 20 + cL + 4];
            }
#pragma unroll
            for (int nt = 0; nt < 4; nt++) {
                int nn = wn + nt * 8 + (lane >> 2);
                bf[nt][0] = Bs[cL * 136 + nn];
                bf[nt][1] = Bs[(cL + 4) * 136 + nn];
            }
#pragma unroll
            for (int mt = 0; mt < 4; mt++)
#pragma unroll
                for (int nt = 0; nt < 4; nt++) mma8(acc[mt][nt], af[mt], bf[nt]);
        }
    };

    const int NK = K3 / 16;
    loadT(0); storeT(); __syncthreads();
    for (int kb = 0; kb < NK; kb++) {
        bool more = kb + 1 < NK;
        if (more) loadT(kb + 1);
        compute();
        __syncthreads();
        if (more) { storeT(); __syncthreads(); }
    }

    float* t3b = g_t3 + (size_t)n * (CC * HWL);
#pragma unroll
    for (int mt = 0; mt < 4; mt++)
#pragma unroll
        for (int nt = 0; nt < 4; nt++) {
            int row = m0 + wm + mt * 16 + (lane >> 2);
            int col = p0 + wn + nt * 8 + (lane & 3) * 2;
            if (col < HWL) {
                *reinterpret_cast<float2*>(&t3b[(size_t)row * HWL + col]) =
                    make_float2(acc[mt][nt][0], acc[mt][nt][1]);
                *reinterpret_cast<float2*>(&t3b[(size_t)(row + 8) * HWL + col]) =
                    make_float2(acc[mt][nt][2], acc[mt][nt][3]);
            }
        }
}

// =====================================================================
// Stage 2: t7[n,k,c'] = p7w[k,c'] * (1/56) * sum_p t2[n,k,p] * x[n,c',p]
//   A = t2 (row-major [k][p]) in smem [128][20]
//   B = x  (row-major [c'][p]) in smem [128][20]
// =====================================================================
__global__ __launch_bounds__(256) void k2(const float* __restrict__ x,
                                          const float* __restrict__ p7w) {
    __shared__ uint32_t As[128 * 20];
    __shared__ uint32_t Bs[128 * 20];
    const int t = threadIdx.x, lane = t & 31, warp = t >> 5;
    const int n = blockIdx.z, m0 = blockIdx.y * 128, c0 = blockIdx.x * 128;
    const int wm = (warp & 1) * 64, wn = (warp >> 1) * 32;
    const float* xb = x + (size_t)n * (CC * HWL);

    float acc[4][4][4];
#pragma unroll
    for (int i = 0; i < 4; i++)
#pragma unroll
        for (int j = 0; j < 4; j++)
#pragma unroll
            for (int r = 0; r < 4; r++) acc[i][j][r] = 0.f;

    const int am = t >> 1, ap = (t & 1) * 8;
    // A row: k-index m0+am -> rolled channel + tap shift
    const int kA = m0 + am;
    const int cA = kA / 3, tapA = kA - 3 * cA;
    const int shA = 2 * tapA - 2;
    const int csrc = (cA + 255) & 255;
    const float* arow = xb + (size_t)csrc * HWL;
    const float* brow = xb + (size_t)(c0 + am) * HWL;

    float va[8], vb[8];
    auto loadT = [&](int kb) {
        int p = kb * 16 + ap;
        int w0 = p % WD;
        const float* srcA = arow + p + shA;
#pragma unroll
        for (int j = 0; j < 8; j++)
            va[j] = ((unsigned)(w0 + j + shA) < WD) ? srcA[j] : 0.f;
        float4 b0 = *reinterpret_cast<const float4*>(brow + p);
        float4 b1 = *reinterpret_cast<const float4*>(brow + p + 4);
        vb[0]=b0.x; vb[1]=b0.y; vb[2]=b0.z; vb[3]=b0.w;
        vb[4]=b1.x; vb[5]=b1.y; vb[6]=b1.z; vb[7]=b1.w;
    };
    auto storeT = [&]() {
#pragma unroll
        for (int j = 0; j < 8; j++) As[am * 20 + ap + j] = f2tf(va[j]);
#pragma unroll
        for (int j = 0; j < 8; j++) Bs[am * 20 + ap + j] = f2tf(vb[j]);
    };
    auto compute = [&]() {
#pragma unroll
        for (int kk = 0; kk < 16; kk += 8) {
            uint32_t af[4][4], bf[4][2];
            int cL = kk + (lane & 3);
#pragma unroll
            for (int mt = 0; mt < 4; mt++) {
                int r = wm + mt * 16 + (lane >> 2);
                af[mt][0] = As[r * 20 + cL];
                af[mt][1] = As[(r + 8) * 20 + cL];
                af[mt][2] = As[r * 20 + cL + 4];
                af[mt][3] = As[(r + 8) * 20 + cL + 4];
            }
#pragma unroll
            for (int nt = 0; nt < 4; nt++) {
                int nn = wn + nt * 8 + (lane >> 2);
                bf[nt][0] = Bs[nn * 20 + cL];
                bf[nt][1] = Bs[nn * 20 + cL + 4];
            }
#pragma unroll
            for (int mt = 0; mt < 4; mt++)
#pragma unroll
                for (int nt = 0; nt < 4; nt++) mma8(acc[mt][nt], af[mt], bf[nt]);
        }
    };

    const int NK = HWL / 16;   // 196
    loadT(0); storeT(); __syncthreads();
    for (int kb = 0; kb < NK; kb++) {
        bool more = kb + 1 < NK;
        if (more) loadT(kb + 1);
        compute();
        __syncthreads();
        if (more) { storeT(); __syncthreads(); }
    }

    float* t7b = g_t7 + (size_t)n * (K3 * CC);
#pragma unroll
    for (int mt = 0; mt < 4; mt++)
#pragma unroll
        for (int nt = 0; nt < 4; nt++) {
            int row = m0 + wm + mt * 16 + (lane >> 2);
            int col = c0 + wn + nt * 8 + (lane & 3) * 2;
            float2 w0 = *reinterpret_cast<const float2*>(&p7w[(size_t)row * CC + col]);
            float2 w1 = *reinterpret_cast<const float2*>(&p7w[(size_t)(row + 8) * CC + col]);
            *reinterpret_cast<float2*>(&t7b[(size_t)row * CC + col]) =
                make_float2(acc[mt][nt][0] * INV56 * w0.x, acc[mt][nt][1] * INV56 * w0.y);
            *reinterpret_cast<float2*>(&t7b[(size_t)(row + 8) * CC + col]) =
                make_float2(acc[mt][nt][2] * INV56 * w1.x, acc[mt][nt][3] * INV56 * w1.y);
        }
}

// =====================================================================
// Stage 3: out[n,c',p] = (1/sqrt(768)) * sum_k t7[n,k,c'] * t6[n,k,p]
//   A = t7 (k-major [k][c']) in smem [16][136]
//   B = t6 (k-major [k][p])  in smem [16][136]
// =====================================================================
__global__ __launch_bounds__(256) void k3(const float* __restrict__ x,
                                          float* __restrict__ out) {
    __shared__ uint32_t As[16 * 136];
    __shared__ uint32_t Bs[16 * 136];
    const int t = threadIdx.x, lane = t & 31, warp = t >> 5;
    const int n = blockIdx.z, m0 = blockIdx.y * 128, p0 = blockIdx.x * 128;
    const int wm = (warp & 1) * 64, wn = (warp >> 1) * 32;
    const float* xb  = x    + (size_t)n * (CC * HWL);
    const float* t3b = g_t3 + (size_t)n * (CC * HWL);
    const float* t7b = g_t7 + (size_t)n * (K3 * CC);

    float acc[4][4][4];
#pragma unroll
    for (int i = 0; i < 4; i++)
#pragma unroll
        for (int j = 0; j < 4; j++)
#pragma unroll
            for (int r = 0; r < 4; r++) acc[i][j][r] = 0.f;

    const int ak3 = t >> 4, amn = (t & 15) * 8;     // A gen: row k, 8 c'
    const int bk = t >> 4, bp = (t & 15) * 8;       // B gen: row k, 8 p
    const int pB = p0 + bp;
    const bool pOK = pB < HWL;
    const int w0 = pOK ? pB % WD : 0;

    float va[8], vb[8];
    auto loadT = [&](int kb) {
        int k0 = kb * 16;
        const float* arow = t7b + (size_t)(k0 + ak3) * CC + m0 + amn;
        float4 a0 = *reinterpret_cast<const float4*>(arow);
        float4 a1 = *reinterpret_cast<const float4*>(arow + 4);
        va[0]=a0.x; va[1]=a0.y; va[2]=a0.z; va[3]=a0.w;
        va[4]=a1.x; va[5]=a1.y; va[6]=a1.z; va[7]=a1.w;
        int k = k0 + bk;
        int c = k / 3, tap = k - 3 * c;
        int sh = 2 * tap - 2;
        const float* srcx = xb  + (size_t)c * HWL + pB + sh;
        const float* srct = t3b + (size_t)c * HWL + pB;
#pragma unroll
        for (int j = 0; j < 8; j++) {
            if (pOK) {
                float s = ((unsigned)(w0 + j + sh) < WD) ? __sinf(HALF_PI * srcx[j]) : 0.f;
                vb[j] = fmaxf(srct[j], s);
            } else vb[j] = 0.f;
        }
    };
    auto storeT = [&]() {
#pragma unroll
        for (int j = 0; j < 8; j++) As[ak3 * 136 + amn + j] = f2tf(va[j]);
#pragma unroll
        for (int j = 0; j < 8; j++) Bs[bk * 136 + bp + j] = f2tf(vb[j]);
    };
    auto compute = [&]() {
#pragma unroll
        for (int kk = 0; kk < 16; kk += 8) {
            uint32_t af[4][4], bf[4][2];
            int cL = kk + (lane & 3);
#pragma unroll
            for (int mt = 0; mt < 4; mt++) {
                int r = wm + mt * 16 + (lane >> 2);
                af[mt][0] = As[cL * 136 + r];
                af[mt][1] = As[cL * 136 + r + 8];
                af[mt][2] = As[(cL + 4) * 136 + r];
                af[mt][3] = As[(cL + 4) * 136 + r + 8];
            }
#pragma unroll
            for (int nt = 0; nt < 4; nt++) {
                int nn = wn + nt * 8 + (lane >> 2);
                bf[nt][0] = Bs[cL * 136 + nn];
                bf[nt][1] = Bs[(cL + 4) * 136 + nn];
            }
#pragma unroll
            for (int mt = 0; mt < 4; mt++)
#pragma unroll
                for (int nt = 0; nt < 4; nt++) mma8(acc[mt][nt], af[mt], bf[nt]);
        }
    };

    const int NK = K3 / 16;
    loadT(0); storeT(); __syncthreads();
    for (int kb = 0; kb < NK; kb++) {
        bool more = kb + 1 < NK;
        if (more) loadT(kb + 1);
        compute();
        __syncthreads();
        if (more) { storeT(); __syncthreads(); }
    }

#pragma unroll
    for (int mt = 0; mt < 4; mt++)
#pragma unroll
        for (int nt = 0; nt < 4; nt++) {
            int row = m0 + wm + mt * 16 + (lane >> 2);
            int col = p0 + wn + nt * 8 + (lane & 3) * 2;
            if (col < HWL) {
                float* o0 = out + ((size_t)n * CC + row) * HWL + col;
                float* o1 = out + ((size_t)n * CC + row + 8) * HWL + col;
                *reinterpret_cast<float2*>(o0) =
                    make_float2(acc[mt][nt][0] * RS768, acc[mt][nt][1] * RS768);
                *reinterpret_cast<float2*>(o1) =
                    make_float2(acc[mt][nt][2] * RS768, acc[mt][nt][3] * RS768);
            }
        }
}

extern "C" void kernel_launch(void* const* d_in, const int* in_sizes, int n_in,
                              void* d_out, int out_size) {
    const float* x   = (const float*)d_in[0];   // (16, 256, 56, 56)
    const float* W3  = (const float*)d_in[1];   // (256, 768)
    const float* p7w = (const float*)d_in[2];   // (1, 256, 3, 256)
    float* out = (float*)d_out;                 // (16, 256, 56, 56)

    k1<<<dim3(25, 2, 16), 256>>>(x, W3);
    k2<<<dim3(2, 6, 16), 256>>>(x, p7w);
    k3<<<dim3(25, 2, 16), 256>>>(x, out);
}